// round 4
// baseline (speedup 1.0000x reference)
#include <cuda_runtime.h>
#include <cstdint>

// Problem constants
#define N_TILES 1024
#define PTS     256
#define IN_F    256
#define OUT_F   256
#define OMEGA   30.0f

// Tiling
#define BM 128
#define BN 128
#define KC 32          // K chunk per stage
#define NSTAGE_ITERS (IN_F / KC)   // 8
#define THREADS 256

// SMEM: A buf 128x32 f32 = 16KB, B buf 32x128 f32 = 16KB, double buffered = 64KB
#define A_BUF_BYTES (BM * KC * 4)
#define B_BUF_BYTES (KC * BN * 4)
#define SMEM_BYTES  (2 * (A_BUF_BYTES + B_BUF_BYTES))
#define B_BASE_OFF  (2 * A_BUF_BYTES)

__device__ int g_idx[N_TILES];

// ---------------------------------------------------------------------------
// Index decode: handles indices delivered as int32 OR int64.
// If int64, every odd 32-bit word (high half) of the first 4KB is 0
// (values are in [0,1024)). For int32 data those words are random indices;
// P(all 512 zero) ~ (1/1024)^512 ~ 0.
// ---------------------------------------------------------------------------
__global__ void decode_indices_kernel(const void* p) {
    __shared__ int s_not64;
    const int t = threadIdx.x;
    if (t == 0) s_not64 = 0;
    __syncthreads();
    const int* pi = (const int*)p;
    if (t < 512 && pi[2 * t + 1] != 0) s_not64 = 1;
    __syncthreads();
    int v;
    if (s_not64) v = pi[t];
    else         v = (int)((const long long*)p)[t];
    g_idx[t] = v;
}

// ---------------------------------------------------------------------------
// Helpers
// ---------------------------------------------------------------------------
__device__ __forceinline__ unsigned f2tf32(float f) {
    unsigned r;
    asm("cvt.rna.tf32.f32 %0, %1;" : "=r"(r) : "f"(f));
    return r;
}

__device__ __forceinline__ void mma_tf32(float (&c)[4], const unsigned (&a)[4],
                                         const unsigned (&b)[2]) {
    asm volatile(
        "mma.sync.aligned.m16n8k8.row.col.f32.tf32.tf32.f32 "
        "{%0,%1,%2,%3}, {%4,%5,%6,%7}, {%8,%9}, {%0,%1,%2,%3};"
        : "+f"(c[0]), "+f"(c[1]), "+f"(c[2]), "+f"(c[3])
        : "r"(a[0]), "r"(a[1]), "r"(a[2]), "r"(a[3]),
          "r"(b[0]), "r"(b[1]));
}

__device__ __forceinline__ void cp16(unsigned dst, const float* src) {
    asm volatile("cp.async.cg.shared.global [%0], [%1], 16;" ::"r"(dst), "l"(src));
}
__device__ __forceinline__ void cp_commit() {
    asm volatile("cp.async.commit_group;");
}
template <int N>
__device__ __forceinline__ void cp_wait() {
    asm volatile("cp.async.wait_group %0;" ::"n"(N));
}

// Fast sine: q = round(x/pi); r = x - q*pi; sin(x) = (-1)^q * poly(r).
// Poly error <= ~1e-7 abs on [-pi/2, pi/2].
__device__ __forceinline__ float fast_sin(float x) {
    float t = x * 0.3183098861837907f;
    int   q = __float2int_rn(t);
    float fq = __int2float_rn(q);
    float r = fmaf(fq, -3.14159274101257f, x);   // PI_HI = float(pi)
    r = fmaf(fq, 8.742277657347586e-8f, r);      // -(PI_LO), PI_LO = pi - PI_HI
    float r2 = r * r;
    float p = fmaf(r2, 2.7525562e-6f, -1.9840874e-4f);
    p = fmaf(r2, p, 8.3333310e-3f);
    p = fmaf(r2, p, -1.6666667e-1f);
    p = fmaf(r2 * r, p, r);
    return __int_as_float(__float_as_int(p) ^ (q << 31));
}

// ---------------------------------------------------------------------------
// Main GEMM + sin kernel.
// grid = (4, 1024): blockIdx.x = quadrant (fastest -> co-resident per tile),
// blockIdx.y = tile. Each CTA: 128x128 output, K=256.
// 256 threads = 8 warps in 2 (M) x 4 (N); warp tile 64x32; mma m16n8k8 tf32.
// ---------------------------------------------------------------------------
extern "C" __global__ void __launch_bounds__(THREADS, 2)
adaptive_sin_gemm(const float* __restrict__ x,
                  const float* __restrict__ weight,
                  const float* __restrict__ bias,
                  float* __restrict__ out) {
    extern __shared__ char smem[];
    const unsigned sbase = (unsigned)__cvta_generic_to_shared(smem);

    const int t    = blockIdx.y;
    const int quad = blockIdx.x;
    const int m_base = (quad & 1) * BM;
    const int n_base = (quad >> 1) * BN;

    const int tid  = threadIdx.x;
    const int lane = tid & 31;
    const int wid  = tid >> 5;
    const int wm   = wid >> 2;   // 0..1
    const int wn   = wid & 3;    // 0..3
    const int rl   = lane >> 2;  // 0..7 (groupID)
    const int ln4  = lane & 3;   // threadID_in_group
    const int l16  = lane >> 4;  // 0..1 (groupID high bit)
    const int q3   = (lane >> 2) & 3;  // groupID low 2 bits

    const int ch = g_idx[t];
    const float* gA = x + ((size_t)t * PTS + m_base) * IN_F;
    const float* gB = weight + (size_t)ch * (IN_F * OUT_F) + n_base;

    float acc[4][4][4];
#pragma unroll
    for (int i = 0; i < 4; i++)
#pragma unroll
        for (int j = 0; j < 4; j++)
#pragma unroll
            for (int k = 0; k < 4; k++) acc[i][j][k] = 0.f;

    // ---- async copy issue for stage kt into buffer buf ----
    auto issue = [&](int buf, int kt) {
        const int k0 = kt * KC;
        const unsigned aOff = sbase + buf * A_BUF_BYTES;
        const unsigned bOff = sbase + B_BASE_OFF + buf * B_BUF_BYTES;
#pragma unroll
        for (int i = 0; i < 4; i++) {
            int id = tid + i * THREADS;          // 0..1023
            int row = id >> 3, c8 = id & 7;      // A: 128 rows x 8 chunks
            cp16(aOff + row * 128 + ((c8 ^ (row & 7)) << 4),
                 gA + (size_t)row * IN_F + k0 + c8 * 4);
        }
#pragma unroll
        for (int i = 0; i < 4; i++) {
            int id = tid + i * THREADS;
            int kr = id >> 5, c32 = id & 31;     // B: 32 k-rows x 32 chunks
            cp16(bOff + kr * 512 + ((c32 ^ ((kr & 3) << 1)) << 4),
                 gB + (size_t)(k0 + kr) * OUT_F + c32 * 4);
        }
        cp_commit();
    };

    issue(0, 0);

    for (int kt = 0; kt < NSTAGE_ITERS; kt++) {
        if (kt + 1 < NSTAGE_ITERS) {
            issue((kt + 1) & 1, kt + 1);
            cp_wait<1>();
        } else {
            cp_wait<0>();
        }
        __syncthreads();

        const char* A = smem + (kt & 1) * A_BUF_BYTES;
        const char* B = smem + B_BASE_OFF + (kt & 1) * B_BUF_BYTES;

#pragma unroll
        for (int kki = 0; kki < 4; kki++) {
            const int kk = kki * 8;
            unsigned af[4][4];
#pragma unroll
            for (int sm = 0; sm < 4; sm++) {
                int base = (wm * 64 + sm * 16 + rl) * 128 +
                           (((kk >> 2) ^ rl) << 4) + ln4 * 4;
                af[sm][0] = f2tf32(*(const float*)(A + base));
                af[sm][1] = f2tf32(*(const float*)(A + base + 8 * 128));
                af[sm][2] = f2tf32(*(const float*)(A + (base ^ 16)));
                af[sm][3] = f2tf32(*(const float*)(A + ((base + 8 * 128) ^ 16)));
            }
            unsigned bf[4][2];
#pragma unroll
            for (int sn = 0; sn < 4; sn++) {
                int n0q = wn * 8 + sn * 2;
                int chunk = (n0q + l16) ^ (ln4 << 1);
                int addr = (kk + ln4) * 512 + (chunk << 4) + q3 * 4;
                bf[sn][0] = f2tf32(*(const float*)(B + addr));
                bf[sn][1] = f2tf32(*(const float*)(B + addr + 4 * 512));
            }
#pragma unroll
            for (int sm = 0; sm < 4; sm++)
#pragma unroll
                for (int sn = 0; sn < 4; sn++)
                    mma_tf32(acc[sm][sn], af[sm], bf[sn]);
        }
        __syncthreads();
    }

    // ---- epilogue: bias + sin(OMEGA * z), streaming float2 stores ----
    // __stcs: out is write-once, never re-read -> keep it out of L2 so the
    // x/weight tiles shared by the 4 co-resident quadrant CTAs stay resident.
    float2 bv[4];
#pragma unroll
    for (int sn = 0; sn < 4; sn++) {
        int n0 = n_base + wn * 32 + sn * 8 + 2 * ln4;
        bv[sn] = *(const float2*)(bias + n0);
    }

#pragma unroll
    for (int sm = 0; sm < 4; sm++) {
        const int r0 = m_base + wm * 64 + sm * 16 + rl;
#pragma unroll
        for (int sn = 0; sn < 4; sn++) {
            const int c0 = n_base + wn * 32 + sn * 8 + 2 * ln4;
            float* o0 = out + ((size_t)t * PTS + r0) * OUT_F + c0;
            float* o1 = o0 + 8 * OUT_F;
            float2 v0, v1;
            v0.x = fast_sin(OMEGA * (acc[sm][sn][0] + bv[sn].x));
            v0.y = fast_sin(OMEGA * (acc[sm][sn][1] + bv[sn].y));
            v1.x = fast_sin(OMEGA * (acc[sm][sn][2] + bv[sn].x));
            v1.y = fast_sin(OMEGA * (acc[sm][sn][3] + bv[sn].y));
            __stcs((float2*)o0, v0);
            __stcs((float2*)o1, v1);
        }
    }
}

// ---------------------------------------------------------------------------
extern "C" void kernel_launch(void* const* d_in, const int* in_sizes, int n_in,
                              void* d_out, int out_size) {
    const float* x      = (const float*)d_in[0];
    const float* weight = (const float*)d_in[1];
    const float* bias   = (const float*)d_in[2];
    const void*  indices = d_in[3];
    float* out = (float*)d_out;

    // Unconditional (idempotent, non-enqueuing, capture-safe). No static guards.
    cudaFuncSetAttribute(adaptive_sin_gemm,
                         cudaFuncAttributeMaxDynamicSharedMemorySize,
                         SMEM_BYTES);

    decode_indices_kernel<<<1, N_TILES>>>(indices);

    dim3 grid(4, N_TILES);   // quadrant fastest -> tile's 4 CTAs co-resident in L2
    adaptive_sin_gemm<<<grid, THREADS, SMEM_BYTES>>>(x, weight, bias, out);
}